// round 15
// baseline (speedup 1.0000x reference)
#include <cuda_runtime.h>
#include <cuda_fp16.h>
#include <cstdint>
#include <math.h>

#define BQ 4
#define TQ 2048
#define DQ 1024
#define BTQ 8192                 // B*T
#define NTT (TQ*TQ)              // 4194304
#define NBTD (BTQ*DQ)            // 8388608
#define PERB (TQ*DQ)             // 2097152

// ------------------------- scratch (device globals) -------------------------
__device__ __half g_ewc[NTT];                         // fp16 of expm1(wbias)
__device__ __half g_xh[NBTD];                         // fp16 x
__device__ __half g_wt[4][DQ*DQ];                     // transposed weights, fp16
__device__ float  g_qsig[NBTD];
__device__ __half g_ekt[NBTD], g_ekvt[NBTD];          // fp16 [b][d][s]
__device__ float  g_partk[128*DQ], g_partkv[128*DQ];  // per-64-s-block partial colsums
__device__ float  g_sumkv[BQ*DQ], g_sumk[BQ*DQ];      // colsums over s
__device__ __half g_oph[NBTD];                        // fp16 op

// ------------------------------- helpers ------------------------------------
__device__ __forceinline__ uint32_t smem_u32(const void* p){
    uint32_t a;
    asm("{ .reg .u64 t; cvta.to.shared.u64 t, %1; cvt.u32.u64 %0, t; }" : "=r"(a) : "l"(p));
    return a;
}
__device__ __forceinline__ void ldsm4(uint32_t* r, uint32_t addr){
    asm volatile("ldmatrix.sync.aligned.m8n8.x4.shared.b16 {%0,%1,%2,%3}, [%4];"
        : "=r"(r[0]),"=r"(r[1]),"=r"(r[2]),"=r"(r[3]) : "r"(addr));
}
__device__ __forceinline__ void mma_f16(float* d, const uint32_t* a, const uint32_t* b){
    asm volatile("mma.sync.aligned.m16n8k16.row.col.f32.f16.f16.f32 "
        "{%0,%1,%2,%3}, {%4,%5,%6,%7}, {%8,%9}, {%0,%1,%2,%3};"
        : "+f"(d[0]),"+f"(d[1]),"+f"(d[2]),"+f"(d[3])
        : "r"(a[0]),"r"(a[1]),"r"(a[2]),"r"(a[3]), "r"(b[0]),"r"(b[1]));
}
__device__ __forceinline__ void cp16(uint32_t saddr, const void* g){
    asm volatile("cp.async.cg.shared.global [%0], [%1], 16;" :: "r"(saddr), "l"(g));
}
__device__ __forceinline__ uint32_t pk2h(__half a, __half b){
    return (uint32_t)__half_as_ushort(a) | ((uint32_t)__half_as_ushort(b) << 16);
}

// row x 32-elem (64B) rows, XOR-swizzled: 16B-aligned, LDSM conflict-free
__device__ __forceinline__ uint32_t swz(uint32_t row, uint32_t chunk){
    return row*64u + (((chunk ^ (row >> 1)) & 3u) << 4);
}

#define A_TILE 4096                    // 64 rows x 64B
#define B_TILE 8192                    // 128 rows x 64B
#define STG    (A_TILE + B_TILE)       // 12288
#define NST    6
#define GEMM_SMEM (NST * STG)          // 73728

// --------------------------- shared mainloop --------------------------------
// acc[2][4][4] += A[m0:m0+64,:] @ [B0(64 rows); B1(64 rows)]^T over K.
// CTA tile 64x128, 8 warps (2x4), warp tile 32x32. fp16 single-pass.
// Paired k-tiles, one barrier per pair, 6 stages, two pairs in flight.
__device__ __forceinline__ void mma_mainloop(
    uint32_t sb, const char* A, const char* B0, const char* B1,
    int K, int m0, int tid, int wm, int wn, int lane, float acc[2][4][4])
{
    const int KT = K >> 5;

    // hoisted per-thread issue addressing
    uint32_t soffA, soffB[2];
    const char* gA;
    const char* gB[2];
    {
        uint32_t row = (uint32_t)(tid >> 2), ch = (uint32_t)(tid & 3);
        soffA = swz(row, ch);
        gA = A + (((size_t)m0 + row)*K + ch*8)*2;
    }
    #pragma unroll
    for (int hh = 0; hh < 2; hh++){
        int c = (hh << 8) + tid;
        uint32_t row = (uint32_t)(c >> 2), ch = (uint32_t)(c & 3);   // 0..127
        soffB[hh] = swz(row, ch);
        gB[hh] = (row < 64) ? B0 + ((size_t)row*K + ch*8)*2
                            : B1 + ((size_t)(row - 64)*K + ch*8)*2;
    }

    auto issue = [&](int kt, int stage){
        uint32_t sbase = sb + stage*STG;
        size_t ko = (size_t)kt * 64;
        cp16(sbase + soffA, gA + ko);
        #pragma unroll
        for (int hh = 0; hh < 2; hh++)
            cp16(sbase + A_TILE + soffB[hh], gB[hh] + ko);
        asm volatile("cp.async.commit_group;" ::: "memory");
    };

    uint32_t a_row = wm*32 + (lane & 15);
    uint32_t a_ch0 = (lane >> 4) & 1;
    uint32_t b_row = wn*32 + ((lane >> 4) & 1)*8 + (lane & 7);
    uint32_t b_ch0 = (lane >> 3) & 1;

    auto compute = [&](int kt){
        uint32_t st = sb + (kt % NST)*STG;
        #pragma unroll
        for (uint32_t j = 0; j < 2; j++){
            uint32_t ca = j*2 + a_ch0;
            uint32_t cb = j*2 + b_ch0;
            uint32_t a[2][4], b[2][4];
            #pragma unroll
            for (uint32_t q = 0; q < 2; q++)
                ldsm4(b[q], st + A_TILE + swz(b_row + q*16, cb));
            #pragma unroll
            for (uint32_t i = 0; i < 2; i++)
                ldsm4(a[i], st + swz(a_row + i*16, ca));
            #pragma unroll
            for (int i = 0; i < 2; i++)
                #pragma unroll
                for (int f = 0; f < 4; f++)
                    mma_f16(acc[i][f], a[i], &b[f>>1][(f&1)*2]);
        }
    };

    issue(0, 0);
    issue(1, 1);
    issue(2, 2);
    issue(3, 3);
    for (int kt = 0; kt < KT; kt += 2){
        if (kt + 2 < KT) asm volatile("cp.async.wait_group 2;" ::: "memory");
        else             asm volatile("cp.async.wait_group 0;" ::: "memory");
        __syncthreads();
        if (kt + 4 < KT){
            issue(kt + 4, (kt + 4) % NST);
            issue(kt + 5, (kt + 5) % NST);
        }
        compute(kt);
        compute(kt + 1);
    }
}

// std epilogue: C[m0..+64, n0..+128] = mode(acc + bias), f32, row stride DQ
__device__ __forceinline__ void epi_std(float acc[2][4][4], float* C, const float* bias,
                                        int mode, int m0, int n0, int wm, int wn, int lane)
{
    int mb = m0 + wm*32 + (lane >> 2);
    int nb = n0 + wn*32 + (lane & 3)*2;
    #pragma unroll
    for (int i = 0; i < 2; i++){
        #pragma unroll
        for (int f = 0; f < 4; f++){
            int row = mb + i*16;
            int col = nb + f*8;
            float v0 = acc[i][f][0], v1 = acc[i][f][1];
            float v2 = acc[i][f][2], v3 = acc[i][f][3];
            if (bias){
                float b0 = __ldg(bias + col), b1 = __ldg(bias + col + 1);
                v0 += b0; v1 += b1; v2 += b0; v3 += b1;
            }
            if (mode == 1){
                v0 = 1.f/(1.f+expf(-v0)); v1 = 1.f/(1.f+expf(-v1));
                v2 = 1.f/(1.f+expf(-v2)); v3 = 1.f/(1.f+expf(-v3));
            }
            float2 o0; o0.x = v0; o0.y = v1;
            float2 o1; o1.x = v2; o1.y = v3;
            *(float2*)(C + (size_t)row * DQ + col)       = o0;
            *(float2*)(C + (size_t)(row + 8) * DQ + col) = o1;
        }
    }
}

// ------------------------------ proj kernel ---------------------------------
// x: 128 m-blocks of 64 rows. y<8: qsig (n0=y*128). y>=8: K|V pair d0=(y-8)*64.
__global__ void __launch_bounds__(256, 3)
proj_k(const float* __restrict__ bq, const float* __restrict__ bk,
       const float* __restrict__ bv)
{
    extern __shared__ char smem[];
    uint32_t sb = smem_u32(smem);
    int tid = threadIdx.x, wid = tid >> 5, lane = tid & 31;
    int wm = wid & 1, wn = wid >> 1;
    int m0 = blockIdx.x * 64;

    float acc[2][4][4];
    #pragma unroll
    for (int i = 0; i < 2; i++)
        #pragma unroll
        for (int f = 0; f < 4; f++)
            #pragma unroll
            for (int r = 0; r < 4; r++) acc[i][f][r] = 0.f;

    const char *B0, *B1;
    if (blockIdx.y < 8){
        size_t n0 = (size_t)blockIdx.y * 128;
        B0 = (const char*)(g_wt[0] + n0*DQ);
        B1 = B0 + (size_t)64*DQ*2;
    } else {
        size_t d0 = (size_t)(blockIdx.y - 8) * 64;
        B0 = (const char*)(g_wt[1] + d0*DQ);
        B1 = (const char*)(g_wt[2] + d0*DQ);
    }
    mma_mainloop(sb, (const char*)g_xh, B0, B1, DQ, m0, tid, wm, wn, lane, acc);

    if (blockIdx.y < 8){
        epi_std(acc, g_qsig, bq, 1, m0, (int)blockIdx.y*128, wm, wn, lane);
        return;
    }

    // ---- K|V epilogue: ek = exp(K+bk), ekv = ek*(V+bv), write transposed ----
    int d0 = ((int)blockIdx.y - 8) * 64;
    float* se = (float*)smem;                 // [64][129]: cols 0-63 K, 64-127 V
    __syncthreads();
    int mbL = wm*32 + (lane >> 2);
    int nbL = wn*32 + (lane & 3)*2;
    #pragma unroll
    for (int i = 0; i < 2; i++){
        #pragma unroll
        for (int f = 0; f < 4; f++){
            int row = mbL + i*16, col = nbL + f*8;
            float v0 = acc[i][f][0], v1 = acc[i][f][1];
            float v2 = acc[i][f][2], v3 = acc[i][f][3];
            if (col < 64){
                float b0 = __ldg(bk + d0 + col), b1 = __ldg(bk + d0 + col + 1);
                v0 = expf(v0 + b0); v1 = expf(v1 + b1);
                v2 = expf(v2 + b0); v3 = expf(v3 + b1);
            } else {
                float b0 = __ldg(bv + d0 + col - 64), b1 = __ldg(bv + d0 + col - 63);
                v0 += b0; v1 += b1; v2 += b0; v3 += b1;
            }
            se[row*129 + col]     = v0; se[row*129 + col + 1]     = v1;
            se[(row+8)*129 + col] = v2; se[(row+8)*129 + col + 1] = v3;
        }
    }
    __syncthreads();

    int b  = m0 >> 11, s0 = m0 & 2047;
    int d  = tid & 63, sblk = (tid >> 6) * 16;
    __half* pk  = g_ekt  + (size_t)b*PERB + (size_t)(d0 + d)*TQ + s0 + sblk;
    __half* pkv = g_ekvt + (size_t)b*PERB + (size_t)(d0 + d)*TQ + s0 + sblk;
    float psk = 0.f, pskv = 0.f;
    #pragma unroll
    for (int gq = 0; gq < 2; gq++){
        __align__(16) __half hk[8];
        __align__(16) __half hv[8];
        #pragma unroll
        for (int s = 0; s < 8; s++){
            int sr = sblk + gq*8 + s;
            float e  = se[sr*129 + d];
            float vv = se[sr*129 + d + 64];
            __half h0 = __float2half(e);
            __half h1 = __float2half(e * vv);
            hk[s] = h0; hv[s] = h1;
            psk  += __half2float(h0);
            pskv += __half2float(h1);
        }
        *(uint4*)(pk  + gq*8) = *(const uint4*)hk;
        *(uint4*)(pkv + gq*8) = *(const uint4*)hv;
    }

    // deterministic partial colsum: 4 s-groups -> 1 per (d, CTA)
    float* pr = (float*)smem + 64*129;        // [2][4][64]
    __syncthreads();
    pr[(tid >> 6)*64 + d]       = psk;
    pr[256 + (tid >> 6)*64 + d] = pskv;
    __syncthreads();
    if (tid < 128){
        int which = tid >> 6, dl = tid & 63;
        const float* p = pr + which*256;
        float s = p[dl] + p[64 + dl] + p[128 + dl] + p[192 + dl];
        (which ? g_partkv : g_partk)[(size_t)blockIdx.x*DQ + d0 + dl] = s;
    }
}

// ---------------------- colsum reduce (32 partials) --------------------------
__global__ void k_colsum_red(){
    int i = blockIdx.x*256 + threadIdx.x;     // 0..8191
    int which = i >> 12;                      // 0: k, 1: kv
    int bd = i & 4095;
    int b = bd >> 10, dd = bd & 1023;
    const float* src = (which ? g_partkv : g_partk);
    float s = 0.f;
    #pragma unroll
    for (int j = 0; j < 32; j++)
        s += src[(size_t)(b*32 + j)*DQ + dd];
    (which ? g_sumkv : g_sumk)[bd] = s;
}

// ------------------------------- mix kernel ---------------------------------
// ONE pass: acc = (ew-1)[t0..+64] @ [ekvt|ekt d0..+64]^T over s.
// epilogue adds colsums, op = q*num/den -> g_oph.
__global__ void __launch_bounds__(256, 3)
mix_k()
{
    extern __shared__ char smem[];
    uint32_t sb = smem_u32(smem);
    int tid = threadIdx.x, wid = tid >> 5, lane = tid & 31;
    int wm = wid & 1, wn = wid >> 1;
    int t0 = blockIdx.x * 64;
    int d0 = blockIdx.y * 64;
    int b  = blockIdx.z;

    float acc[2][4][4];
    #pragma unroll
    for (int i = 0; i < 2; i++)
        #pragma unroll
        for (int f = 0; f < 4; f++)
            #pragma unroll
            for (int r = 0; r < 4; r++) acc[i][f][r] = 0.f;

    const char* B0 = (const char*)(g_ekvt + (size_t)b*PERB + (size_t)d0*TQ);
    const char* B1 = (const char*)(g_ekt  + (size_t)b*PERB + (size_t)d0*TQ);
    mma_mainloop(sb, (const char*)g_ewc, B0, B1, TQ, t0, tid, wm, wn, lane, acc);

    float* se = (float*)smem;                 // [64][129]: 0-63 num, 64-127 den
    __syncthreads();
    int mbL = wm*32 + (lane >> 2);
    int nbL = wn*32 + (lane & 3)*2;
    #pragma unroll
    for (int i = 0; i < 2; i++){
        #pragma unroll
        for (int f = 0; f < 4; f++){
            int row = mbL + i*16, col = nbL + f*8;
            se[row*129 + col]     = acc[i][f][0]; se[row*129 + col + 1]     = acc[i][f][1];
            se[(row+8)*129 + col] = acc[i][f][2]; se[(row+8)*129 + col + 1] = acc[i][f][3];
        }
    }
    __syncthreads();

    int t = tid >> 2, dq = (tid & 3) * 16;
    size_t obase = (size_t)b*PERB + (size_t)(t0 + t)*DQ + d0 + dq;
    const float* qp  = g_qsig  + obase;
    const float* skv = g_sumkv + b*DQ + d0 + dq;
    const float* sk  = g_sumk  + b*DQ + d0 + dq;
    __half* ph = g_oph + obase;
    #pragma unroll
    for (int gq = 0; gq < 2; gq++){
        __align__(16) __half hh[8];
        #pragma unroll
        for (int s = 0; s < 8; s++){
            int c = dq + gq*8 + s;
            float num = se[t*129 + c]      + __ldg(skv + gq*8 + s);
            float den = se[t*129 + 64 + c] + __ldg(sk  + gq*8 + s);
            float q   = __ldg(qp + gq*8 + s);
            hh[s] = __float2half(q * num / den);
        }
        *(uint4*)(ph + gq*8) = *(const uint4*)hh;
    }
}

// ------------------------------- out kernel ---------------------------------
__global__ void __launch_bounds__(256, 3)
out_k(float* __restrict__ out, const float* __restrict__ bo)
{
    extern __shared__ char smem[];
    uint32_t sb = smem_u32(smem);
    int tid = threadIdx.x, wid = tid >> 5, lane = tid & 31;
    int wm = wid & 1, wn = wid >> 1;
    int m0 = blockIdx.x * 64, n0 = blockIdx.y * 128;

    float acc[2][4][4];
    #pragma unroll
    for (int i = 0; i < 2; i++)
        #pragma unroll
        for (int f = 0; f < 4; f++)
            #pragma unroll
            for (int r = 0; r < 4; r++) acc[i][f][r] = 0.f;

    const char* B0 = (const char*)(g_wt[3] + (size_t)n0*DQ);
    const char* B1 = B0 + (size_t)64*DQ*2;
    mma_mainloop(sb, (const char*)g_oph, B0, B1, DQ, m0, tid, wm, wn, lane, acc);
    epi_std(acc, out, bo, 0, m0, n0, wm, wn, lane);
}

// --------------------------- elementwise / prep ------------------------------
__global__ void k_splith(const float* __restrict__ in){
    size_t i = (size_t)blockIdx.x * blockDim.x + threadIdx.x;
    float4 v = ((const float4*)in)[i];
    ((uint2*)g_xh)[i] = make_uint2(pk2h(__float2half(v.x), __float2half(v.y)),
                                   pk2h(__float2half(v.z), __float2half(v.w)));
}

__global__ void k_ew(const float* __restrict__ wb){
    size_t i = (size_t)blockIdx.x * blockDim.x + threadIdx.x;
    float4 v = ((const float4*)wb)[i];
    ((uint2*)g_ewc)[i] = make_uint2(
        pk2h(__float2half(expm1f(v.x)), __float2half(expm1f(v.y))),
        pk2h(__float2half(expm1f(v.z)), __float2half(expm1f(v.w))));
}

// transpose all four weights W_z[DQ,DQ] -> g_wt[z] (single fp16)
__global__ void k_tsplit4(const float* __restrict__ W0, const float* __restrict__ W1,
                          const float* __restrict__ W2, const float* __restrict__ W3){
    __shared__ float t[32][33];
    int z = blockIdx.z;
    const float* W = (z == 0) ? W0 : (z == 1) ? W1 : (z == 2) ? W2 : W3;
    __half* tw = g_wt[z];
    int x  = blockIdx.x*32 + threadIdx.x;
    int y0 = blockIdx.y*32;
    for (int j = threadIdx.y; j < 32; j += 8)
        t[j][threadIdx.x] = W[(size_t)(y0 + j)*DQ + x];
    __syncthreads();
    int x2  = y0 + threadIdx.x;
    int y20 = blockIdx.x*32;
    for (int j = threadIdx.y; j < 32; j += 8)
        tw[(size_t)(y20 + j)*DQ + x2] = __float2half(t[threadIdx.x][j]);
}

// --------------------------------- host -------------------------------------
extern "C" void kernel_launch(void* const* d_in, const int* in_sizes, int n_in,
                              void* d_out, int out_size){
    (void)in_sizes; (void)n_in; (void)out_size;
    const float* x  = (const float*)d_in[0];
    const float* Wq = (const float*)d_in[1];
    const float* bq = (const float*)d_in[2];
    const float* Wk = (const float*)d_in[3];
    const float* bk = (const float*)d_in[4];
    const float* Wv = (const float*)d_in[5];
    const float* bv = (const float*)d_in[6];
    const float* Wo = (const float*)d_in[7];
    const float* bo = (const float*)d_in[8];
    const float* wb = (const float*)d_in[9];
    float* out = (float*)d_out;

    cudaFuncSetAttribute(proj_k, cudaFuncAttributeMaxDynamicSharedMemorySize, GEMM_SMEM);
    cudaFuncSetAttribute(mix_k,  cudaFuncAttributeMaxDynamicSharedMemorySize, GEMM_SMEM);
    cudaFuncSetAttribute(out_k,  cudaFuncAttributeMaxDynamicSharedMemorySize, GEMM_SMEM);

    dim3 tb(32, 8);
    k_tsplit4<<<dim3(32, 32, 4), tb>>>(Wq, Wk, Wv, Wo);
    k_splith<<<NBTD/1024, 256>>>(x);
    k_ew<<<NTT/1024, 256>>>(wb);

    // proj: y<8 qsig, y>=8 fused K|V -> ekt/ekvt + partial colsums
    proj_k<<<dim3(128, 24), 256, GEMM_SMEM>>>(bq, bk, bv);

    // reduce 32 partials -> colsums
    k_colsum_red<<<32, 256>>>();

    // mix: single-pass centered GEMM + colsum correction + op epilogue
    mix_k<<<dim3(32, 16, 4), 256, GEMM_SMEM>>>();

    // out = OP @ Wo + bo (single-pass fp16)
    out_k<<<dim3(128, 8), 256, GEMM_SMEM>>>(out, bo);
}

// round 16
// speedup vs baseline: 1.0899x; 1.0899x over previous
#include <cuda_runtime.h>
#include <cuda_fp16.h>
#include <cstdint>
#include <math.h>

#define BQ 4
#define TQ 2048
#define DQ 1024
#define BTQ 8192                 // B*T
#define NTT (TQ*TQ)              // 4194304
#define NBTD (BTQ*DQ)            // 8388608
#define PERB (TQ*DQ)             // 2097152

// ------------------------- scratch (device globals) -------------------------
__device__ __half g_ewc[NTT];                         // fp16 of expm1(wbias)
__device__ __half g_xh[NBTD];                         // fp16 x
__device__ __half g_wt[4][DQ*DQ];                     // transposed weights, fp16
__device__ __half g_qsig[NBTD];                       // fp16 sigmoid(Q)
__device__ __half g_ekt[NBTD], g_ekvt[NBTD];          // fp16 [b][d][s]
__device__ float  g_partk[64*DQ], g_partkv[64*DQ];    // per-s-block partial colsums
__device__ float  g_sumkv[BQ*DQ], g_sumk[BQ*DQ];      // colsums over s
__device__ __half g_oph[NBTD];                        // fp16 op

// ------------------------------- helpers ------------------------------------
__device__ __forceinline__ uint32_t smem_u32(const void* p){
    uint32_t a;
    asm("{ .reg .u64 t; cvta.to.shared.u64 t, %1; cvt.u32.u64 %0, t; }" : "=r"(a) : "l"(p));
    return a;
}
__device__ __forceinline__ void ldsm4(uint32_t* r, uint32_t addr){
    asm volatile("ldmatrix.sync.aligned.m8n8.x4.shared.b16 {%0,%1,%2,%3}, [%4];"
        : "=r"(r[0]),"=r"(r[1]),"=r"(r[2]),"=r"(r[3]) : "r"(addr));
}
__device__ __forceinline__ void mma_f16(float* d, const uint32_t* a, const uint32_t* b){
    asm volatile("mma.sync.aligned.m16n8k16.row.col.f32.f16.f16.f32 "
        "{%0,%1,%2,%3}, {%4,%5,%6,%7}, {%8,%9}, {%0,%1,%2,%3};"
        : "+f"(d[0]),"+f"(d[1]),"+f"(d[2]),"+f"(d[3])
        : "r"(a[0]),"r"(a[1]),"r"(a[2]),"r"(a[3]), "r"(b[0]),"r"(b[1]));
}
__device__ __forceinline__ void cp16(uint32_t saddr, const void* g){
    asm volatile("cp.async.cg.shared.global [%0], [%1], 16;" :: "r"(saddr), "l"(g));
}
__device__ __forceinline__ uint32_t pk2h(__half a, __half b){
    return (uint32_t)__half_as_ushort(a) | ((uint32_t)__half_as_ushort(b) << 16);
}

// 128-row x 32-elem (64B) tile, XOR-swizzled: 16B-aligned, LDSM conflict-free
#define TILE_BYTES 8192
__device__ __forceinline__ uint32_t swz(uint32_t row, uint32_t chunk){
    return row*64u + (((chunk ^ (row >> 1)) & 3u) << 4);
}

#define NST 6                          // pipeline stages
#define STG (2 * TILE_BYTES)           // 16384 (A + B tile per stage)
#define GEMM_SMEM (NST * STG)          // 98304

// --------------------------- shared mainloop --------------------------------
// acc += A @ [B0(64 rows); B1(64 rows)]^T over K.  A single fp16.
// Paired k-tiles, one barrier per pair, 6 stages, two pairs in flight.
__device__ __forceinline__ void mma_mainloop(
    uint32_t sb, const char* A, const char* B0, const char* B1,
    int K, int m0, int tid, int wm, int wn, int lane, float acc[4][4][4])
{
    const int KT = K >> 5;

    uint32_t soff[2];
    const char* gbase[2][2];
    #pragma unroll
    for (int hh = 0; hh < 2; hh++){
        int c = (hh << 8) + tid;
        uint32_t row = (uint32_t)(c >> 2), ch = (uint32_t)(c & 3);
        soff[hh] = swz(row, ch);
        gbase[0][hh] = A + (((size_t)m0 + row)*K + ch*8)*2;
        gbase[1][hh] = (row < 64) ? B0 + ((size_t)row*K + ch*8)*2
                                  : B1 + ((size_t)(row - 64)*K + ch*8)*2;
    }

    auto issue = [&](int kt, int stage){
        uint32_t sbase = sb + stage*STG;
        size_t ko = (size_t)kt * 64;
        #pragma unroll
        for (int t = 0; t < 2; t++)
            #pragma unroll
            for (int hh = 0; hh < 2; hh++)
                cp16(sbase + t*TILE_BYTES + soff[hh], gbase[t][hh] + ko);
        asm volatile("cp.async.commit_group;" ::: "memory");
    };

    uint32_t a_row = wm*64 + (lane & 15);
    uint32_t a_ch0 = (lane >> 4) & 1;
    uint32_t b_row = wn*32 + ((lane >> 4) & 1)*8 + (lane & 7);
    uint32_t b_ch0 = (lane >> 3) & 1;

    auto compute = [&](int kt){
        uint32_t st = sb + (kt % NST)*STG;
        #pragma unroll
        for (uint32_t j = 0; j < 2; j++){
            uint32_t ca = j*2 + a_ch0;
            uint32_t cb = j*2 + b_ch0;
            uint32_t a[4][4], b[2][4];
            #pragma unroll
            for (uint32_t q = 0; q < 2; q++)
                ldsm4(b[q], st + TILE_BYTES + swz(b_row + q*16, cb));
            #pragma unroll
            for (uint32_t i = 0; i < 4; i++)
                ldsm4(a[i], st + swz(a_row + i*16, ca));
            #pragma unroll
            for (int i = 0; i < 4; i++)
                #pragma unroll
                for (int f = 0; f < 4; f++)
                    mma_f16(acc[i][f], a[i], &b[f>>1][(f&1)*2]);
        }
    };

    issue(0, 0);
    issue(1, 1);
    issue(2, 2);
    issue(3, 3);
    for (int kt = 0; kt < KT; kt += 2){
        if (kt + 2 < KT) asm volatile("cp.async.wait_group 2;" ::: "memory");
        else             asm volatile("cp.async.wait_group 0;" ::: "memory");
        __syncthreads();
        if (kt + 4 < KT){
            issue(kt + 4, (kt + 4) % NST);
            issue(kt + 5, (kt + 5) % NST);
        }
        compute(kt);
        compute(kt + 1);
    }
}

// f32 epilogue (out): C = acc + bias
__device__ __forceinline__ void epi_f32(float acc[4][4][4], float* C, const float* bias,
                                        int m0, int n0, int wm, int wn, int lane)
{
    int mb = m0 + wm*64 + (lane >> 2);
    int nb = n0 + wn*32 + (lane & 3)*2;
    #pragma unroll
    for (int i = 0; i < 4; i++){
        #pragma unroll
        for (int f = 0; f < 4; f++){
            int row = mb + i*16;
            int col = nb + f*8;
            float v0 = acc[i][f][0], v1 = acc[i][f][1];
            float v2 = acc[i][f][2], v3 = acc[i][f][3];
            float b0 = __ldg(bias + col), b1 = __ldg(bias + col + 1);
            v0 += b0; v1 += b1; v2 += b0; v3 += b1;
            float2 o0; o0.x = v0; o0.y = v1;
            float2 o1; o1.x = v2; o1.y = v3;
            *(float2*)(C + (size_t)row * DQ + col)       = o0;
            *(float2*)(C + (size_t)(row + 8) * DQ + col) = o1;
        }
    }
}

// fp16 sigmoid epilogue (qsig)
__device__ __forceinline__ void epi_qsig(float acc[4][4][4], __half* C, const float* bias,
                                         int m0, int n0, int wm, int wn, int lane)
{
    int mb = m0 + wm*64 + (lane >> 2);
    int nb = n0 + wn*32 + (lane & 3)*2;
    #pragma unroll
    for (int i = 0; i < 4; i++){
        #pragma unroll
        for (int f = 0; f < 4; f++){
            int row = mb + i*16;
            int col = nb + f*8;
            float b0 = __ldg(bias + col), b1 = __ldg(bias + col + 1);
            float v0 = 1.f/(1.f+expf(-(acc[i][f][0] + b0)));
            float v1 = 1.f/(1.f+expf(-(acc[i][f][1] + b1)));
            float v2 = 1.f/(1.f+expf(-(acc[i][f][2] + b0)));
            float v3 = 1.f/(1.f+expf(-(acc[i][f][3] + b1)));
            __half2 o0 = __floats2half2_rn(v0, v1);
            __half2 o1 = __floats2half2_rn(v2, v3);
            *(__half2*)(C + (size_t)row * DQ + col)       = o0;
            *(__half2*)(C + (size_t)(row + 8) * DQ + col) = o1;
        }
    }
}

// ------------------------------ proj kernel ---------------------------------
__global__ void __launch_bounds__(256, 2)
proj_k(const float* __restrict__ bq, const float* __restrict__ bk,
       const float* __restrict__ bv)
{
    extern __shared__ char smem[];
    uint32_t sb = smem_u32(smem);
    int tid = threadIdx.x, wid = tid >> 5, lane = tid & 31;
    int wm = wid & 1, wn = wid >> 1;
    int m0 = blockIdx.x * 128;

    float acc[4][4][4];
    #pragma unroll
    for (int i = 0; i < 4; i++)
        #pragma unroll
        for (int f = 0; f < 4; f++)
            #pragma unroll
            for (int r = 0; r < 4; r++) acc[i][f][r] = 0.f;

    const char *B0, *B1;
    if (blockIdx.y < 8){
        size_t n0 = (size_t)blockIdx.y * 128;
        B0 = (const char*)(g_wt[0] + n0*DQ);
        B1 = B0 + (size_t)64*DQ*2;
    } else {
        size_t d0 = (size_t)(blockIdx.y - 8) * 64;
        B0 = (const char*)(g_wt[1] + d0*DQ);
        B1 = (const char*)(g_wt[2] + d0*DQ);
    }
    mma_mainloop(sb, (const char*)g_xh, B0, B1, DQ, m0, tid, wm, wn, lane, acc);

    if (blockIdx.y < 8){
        epi_qsig(acc, g_qsig, bq, m0, (int)blockIdx.y*128, wm, wn, lane);
        return;
    }

    // ---- K|V epilogue: ek = exp(K+bk), ekv = ek*(V+bv), write transposed ----
    int d0 = ((int)blockIdx.y - 8) * 64;
    float* se = (float*)smem;                 // [128][129]
    __syncthreads();
    int mbL = wm*64 + (lane >> 2);
    int nbL = wn*32 + (lane & 3)*2;
    #pragma unroll
    for (int i = 0; i < 4; i++){
        #pragma unroll
        for (int f = 0; f < 4; f++){
            int row = mbL + i*16, col = nbL + f*8;
            float v0 = acc[i][f][0], v1 = acc[i][f][1];
            float v2 = acc[i][f][2], v3 = acc[i][f][3];
            if (col < 64){
                float b0 = __ldg(bk + d0 + col), b1 = __ldg(bk + d0 + col + 1);
                v0 = expf(v0 + b0); v1 = expf(v1 + b1);
                v2 = expf(v2 + b0); v3 = expf(v3 + b1);
            } else {
                float b0 = __ldg(bv + d0 + col - 64), b1 = __ldg(bv + d0 + col - 63);
                v0 += b0; v1 += b1; v2 += b0; v3 += b1;
            }
            se[row*129 + col]     = v0; se[row*129 + col + 1]     = v1;
            se[(row+8)*129 + col] = v2; se[(row+8)*129 + col + 1] = v3;
        }
    }
    __syncthreads();

    int b  = m0 >> 11, s0 = m0 & 2047;
    int d  = tid & 63, sblk = (tid >> 6) * 32;
    __half* pk  = g_ekt  + (size_t)b*PERB + (size_t)(d0 + d)*TQ + s0 + sblk;
    __half* pkv = g_ekvt + (size_t)b*PERB + (size_t)(d0 + d)*TQ + s0 + sblk;
    float psk = 0.f, pskv = 0.f;
    #pragma unroll
    for (int gq = 0; gq < 4; gq++){
        __align__(16) __half hk[8];
        __align__(16) __half hv[8];
        #pragma unroll
        for (int s = 0; s < 8; s++){
            int sr = sblk + gq*8 + s;
            float e  = se[sr*129 + d];
            float vv = se[sr*129 + d + 64];
            __half h0 = __float2half(e);
            __half h1 = __float2half(e * vv);
            hk[s] = h0; hv[s] = h1;
            psk  += __half2float(h0);
            pskv += __half2float(h1);
        }
        *(uint4*)(pk  + gq*8) = *(const uint4*)hk;
        *(uint4*)(pkv + gq*8) = *(const uint4*)hv;
    }

    // deterministic partial colsum: 4 s-groups -> 1 per (d, CTA)
    float* pr = (float*)smem + 128*129;       // [2][4][64]
    __syncthreads();
    pr[(tid >> 6)*64 + d]       = psk;
    pr[256 + (tid >> 6)*64 + d] = pskv;
    __syncthreads();
    if (tid < 128){
        int which = tid >> 6, dl = tid & 63;
        const float* p = pr + which*256;
        float s = p[dl] + p[64 + dl] + p[128 + dl] + p[192 + dl];
        (which ? g_partkv : g_partk)[(size_t)blockIdx.x*DQ + d0 + dl] = s;
    }
}

// ---------------------- colsum reduce (16 partials) --------------------------
__global__ void k_colsum_red(){
    int i = blockIdx.x*256 + threadIdx.x;     // 0..8191
    int which = i >> 12;                      // 0: k, 1: kv
    int bd = i & 4095;
    int b = bd >> 10, dd = bd & 1023;
    const float* src = (which ? g_partkv : g_partk);
    float s = 0.f;
    #pragma unroll
    for (int j = 0; j < 16; j++)
        s += src[(size_t)(b*16 + j)*DQ + dd];
    (which ? g_sumkv : g_sumk)[bd] = s;
}

// ------------------------------- mix kernel ---------------------------------
// ONE pass: acc = (ew-1) @ [ekvt|ekt]^T ; epilogue adds colsums, op = q*num/den
__global__ void __launch_bounds__(256, 2)
mix_k()
{
    extern __shared__ char smem[];
    uint32_t sb = smem_u32(smem);
    int tid = threadIdx.x, wid = tid >> 5, lane = tid & 31;
    int wm = wid & 1, wn = wid >> 1;
    int t0 = blockIdx.x * 128;
    int d0 = blockIdx.y * 64;
    int b  = blockIdx.z;

    float acc[4][4][4];
    #pragma unroll
    for (int i = 0; i < 4; i++)
        #pragma unroll
        for (int f = 0; f < 4; f++)
            #pragma unroll
            for (int r = 0; r < 4; r++) acc[i][f][r] = 0.f;

    const char* B0 = (const char*)(g_ekvt + (size_t)b*PERB + (size_t)d0*TQ);
    const char* B1 = (const char*)(g_ekt  + (size_t)b*PERB + (size_t)d0*TQ);
    mma_mainloop(sb, (const char*)g_ewc, B0, B1, TQ, t0, tid, wm, wn, lane, acc);

    float* se = (float*)smem;                 // [128][129]
    __syncthreads();
    int mbL = wm*64 + (lane >> 2);
    int nbL = wn*32 + (lane & 3)*2;
    #pragma unroll
    for (int i = 0; i < 4; i++){
        #pragma unroll
        for (int f = 0; f < 4; f++){
            int row = mbL + i*16, col = nbL + f*8;
            se[row*129 + col]     = acc[i][f][0]; se[row*129 + col + 1]     = acc[i][f][1];
            se[(row+8)*129 + col] = acc[i][f][2]; se[(row+8)*129 + col + 1] = acc[i][f][3];
        }
    }
    __syncthreads();

    int t = tid >> 1, dq = (tid & 1) * 32;
    size_t obase = (size_t)b*PERB + (size_t)(t0 + t)*DQ + d0 + dq;
    const __half* qp = g_qsig + obase;
    const float* skv = g_sumkv + b*DQ + d0 + dq;
    const float* sk  = g_sumk  + b*DQ + d0 + dq;
    __half* ph = g_oph + obase;
    #pragma unroll
    for (int gq = 0; gq < 4; gq++){
        __align__(16) __half hh[8];
        uint4 qu = *(const uint4*)(qp + gq*8);
        const __half2* qh2 = (const __half2*)&qu;
        #pragma unroll
        for (int s = 0; s < 8; s++){
            int c = dq + gq*8 + s;
            float num = se[t*129 + c]      + __ldg(skv + gq*8 + s);
            float den = se[t*129 + 64 + c] + __ldg(sk  + gq*8 + s);
            float q   = ((s & 1) ? __high2float(qh2[s >> 1]) : __low2float(qh2[s >> 1]));
            hh[s] = __float2half(q * num / den);
        }
        *(uint4*)(ph + gq*8) = *(const uint4*)hh;
    }
}

// ------------------------------- out kernel ---------------------------------
__global__ void __launch_bounds__(256, 2)
out_k(float* __restrict__ out, const float* __restrict__ bo)
{
    extern __shared__ char smem[];
    uint32_t sb = smem_u32(smem);
    int tid = threadIdx.x, wid = tid >> 5, lane = tid & 31;
    int wm = wid & 1, wn = wid >> 1;
    int m0 = blockIdx.x * 128, n0 = blockIdx.y * 128;

    float acc[4][4][4];
    #pragma unroll
    for (int i = 0; i < 4; i++)
        #pragma unroll
        for (int f = 0; f < 4; f++)
            #pragma unroll
            for (int r = 0; r < 4; r++) acc[i][f][r] = 0.f;

    const char* B0 = (const char*)(g_wt[3] + (size_t)n0*DQ);
    const char* B1 = B0 + (size_t)64*DQ*2;
    mma_mainloop(sb, (const char*)g_oph, B0, B1, DQ, m0, tid, wm, wn, lane, acc);
    epi_f32(acc, out, bo, m0, n0, wm, wn, lane);
}

// --------------------------- elementwise / prep ------------------------------
// blocks 0..8191: x -> g_xh (fp16).  blocks 8192..12287: wbias -> g_ewc.
__global__ void k_prep_in(const float* __restrict__ x, const float* __restrict__ wb){
    size_t blk = blockIdx.x;
    if (blk < 8192){
        size_t i = blk * 256 + threadIdx.x;
        float4 v = ((const float4*)x)[i];
        ((uint2*)g_xh)[i] = make_uint2(pk2h(__float2half(v.x), __float2half(v.y)),
                                       pk2h(__float2half(v.z), __float2half(v.w)));
    } else {
        size_t i = (blk - 8192) * 256 + threadIdx.x;
        float4 v = ((const float4*)wb)[i];
        ((uint2*)g_ewc)[i] = make_uint2(
            pk2h(__float2half(expm1f(v.x)), __float2half(expm1f(v.y))),
            pk2h(__float2half(expm1f(v.z)), __float2half(expm1f(v.w))));
    }
}

// transpose all four weights W_z[DQ,DQ] -> g_wt[z] (single fp16)
__global__ void k_tsplit4(const float* __restrict__ W0, const float* __restrict__ W1,
                          const float* __restrict__ W2, const float* __restrict__ W3){
    __shared__ float t[32][33];
    int z = blockIdx.z;
    const float* W = (z == 0) ? W0 : (z == 1) ? W1 : (z == 2) ? W2 : W3;
    __half* tw = g_wt[z];
    int x  = blockIdx.x*32 + threadIdx.x;
    int y0 = blockIdx.y*32;
    for (int j = threadIdx.y; j < 32; j += 8)
        t[j][threadIdx.x] = W[(size_t)(y0 + j)*DQ + x];
    __syncthreads();
    int x2  = y0 + threadIdx.x;
    int y20 = blockIdx.x*32;
    for (int j = threadIdx.y; j < 32; j += 8)
        tw[(size_t)(y20 + j)*DQ + x2] = __float2half(t[threadIdx.x][j]);
}

// --------------------------------- host -------------------------------------
extern "C" void kernel_launch(void* const* d_in, const int* in_sizes, int n_in,
                              void* d_out, int out_size){
    (void)in_sizes; (void)n_in; (void)out_size;
    const float* x  = (const float*)d_in[0];
    const float* Wq = (const float*)d_in[1];
    const float* bq = (const float*)d_in[2];
    const float* Wk = (const float*)d_in[3];
    const float* bk = (const float*)d_in[4];
    const float* Wv = (const float*)d_in[5];
    const float* bv = (const float*)d_in[6];
    const float* Wo = (const float*)d_in[7];
    const float* bo = (const float*)d_in[8];
    const float* wb = (const float*)d_in[9];
    float* out = (float*)d_out;

    cudaFuncSetAttribute(proj_k, cudaFuncAttributeMaxDynamicSharedMemorySize, GEMM_SMEM);
    cudaFuncSetAttribute(mix_k,  cudaFuncAttributeMaxDynamicSharedMemorySize, GEMM_SMEM);
    cudaFuncSetAttribute(out_k,  cudaFuncAttributeMaxDynamicSharedMemorySize, GEMM_SMEM);

    dim3 tb(32, 8);
    k_tsplit4<<<dim3(32, 32, 4), tb>>>(Wq, Wk, Wv, Wo);
    k_prep_in<<<12288, 256>>>(x, wb);

    // proj: y<8 qsig (fp16), y>=8 fused K|V -> ekt/ekvt + partial colsums
    proj_k<<<dim3(64, 24), 256, GEMM_SMEM>>>(bq, bk, bv);

    // reduce 16 partials -> colsums
    k_colsum_red<<<32, 256>>>();

    // mix: single-pass centered GEMM + colsum correction + op epilogue
    mix_k<<<dim3(16, 16, 4), 256, GEMM_SMEM>>>();

    // out = OP @ Wo + bo (single-pass fp16)
    out_k<<<dim3(64, 8), 256, GEMM_SMEM>>>(out, bo);
}

// round 17
// speedup vs baseline: 1.0984x; 1.0078x over previous
#include <cuda_runtime.h>
#include <cuda_fp16.h>
#include <cstdint>
#include <math.h>

#define BQ 4
#define TQ 2048
#define DQ 1024
#define BTQ 8192                 // B*T
#define NTT (TQ*TQ)              // 4194304
#define NBTD (BTQ*DQ)            // 8388608
#define PERB (TQ*DQ)             // 2097152

// ------------------------- scratch (device globals) -------------------------
__device__ __half g_ewc[NTT];                         // fp16 of expm1(wbias)
__device__ __half g_xh[NBTD];                         // fp16 x
__device__ __half g_wt[4][DQ*DQ];                     // transposed weights, fp16
__device__ __half g_qsig[NBTD];                       // fp16 sigmoid(Q)
__device__ __half g_ekt[NBTD], g_ekvt[NBTD];          // fp16 [b][d][s]
__device__ float  g_partk[64*DQ], g_partkv[64*DQ];    // per-s-block partial colsums
__device__ float  g_sumkv[BQ*DQ], g_sumk[BQ*DQ];      // colsums over s
__device__ __half g_oph[NBTD];                        // fp16 op

// ------------------------------- helpers ------------------------------------
__device__ __forceinline__ uint32_t smem_u32(const void* p){
    uint32_t a;
    asm("{ .reg .u64 t; cvta.to.shared.u64 t, %1; cvt.u32.u64 %0, t; }" : "=r"(a) : "l"(p));
    return a;
}
__device__ __forceinline__ void ldsm4(uint32_t* r, uint32_t addr){
    asm volatile("ldmatrix.sync.aligned.m8n8.x4.shared.b16 {%0,%1,%2,%3}, [%4];"
        : "=r"(r[0]),"=r"(r[1]),"=r"(r[2]),"=r"(r[3]) : "r"(addr));
}
__device__ __forceinline__ void mma_f16(float* d, const uint32_t* a, const uint32_t* b){
    asm volatile("mma.sync.aligned.m16n8k16.row.col.f32.f16.f16.f32 "
        "{%0,%1,%2,%3}, {%4,%5,%6,%7}, {%8,%9}, {%0,%1,%2,%3};"
        : "+f"(d[0]),"+f"(d[1]),"+f"(d[2]),"+f"(d[3])
        : "r"(a[0]),"r"(a[1]),"r"(a[2]),"r"(a[3]), "r"(b[0]),"r"(b[1]));
}
__device__ __forceinline__ void cp16(uint32_t saddr, const void* g){
    asm volatile("cp.async.cg.shared.global [%0], [%1], 16;" :: "r"(saddr), "l"(g));
}
__device__ __forceinline__ uint32_t pk2h(__half a, __half b){
    return (uint32_t)__half_as_ushort(a) | ((uint32_t)__half_as_ushort(b) << 16);
}

// 128-row x 32-elem (64B) tile, XOR-swizzled: 16B-aligned, LDSM conflict-free
#define TILE_BYTES 8192
__device__ __forceinline__ uint32_t swz(uint32_t row, uint32_t chunk){
    return row*64u + (((chunk ^ (row >> 1)) & 3u) << 4);
}

#define NST 6                          // pipeline stages
#define STG (2 * TILE_BYTES)           // 16384 (A + B tile per stage)
#define GEMM_SMEM (NST * STG)          // 98304

// --------------------------- shared mainloop --------------------------------
// acc += A @ [B0(64 rows); B1(64 rows)]^T over K.  A single fp16.
// Paired k-tiles, one barrier per pair, 6 stages, two pairs in flight.
__device__ __forceinline__ void mma_mainloop(
    uint32_t sb, const char* A, const char* B0, const char* B1,
    int K, int m0, int tid, int wm, int wn, int lane, float acc[4][4][4])
{
    const int KT = K >> 5;

    uint32_t soff[2];
    const char* gbase[2][2];
    #pragma unroll
    for (int hh = 0; hh < 2; hh++){
        int c = (hh << 8) + tid;
        uint32_t row = (uint32_t)(c >> 2), ch = (uint32_t)(c & 3);
        soff[hh] = swz(row, ch);
        gbase[0][hh] = A + (((size_t)m0 + row)*K + ch*8)*2;
        gbase[1][hh] = (row < 64) ? B0 + ((size_t)row*K + ch*8)*2
                                  : B1 + ((size_t)(row - 64)*K + ch*8)*2;
    }

    auto issue = [&](int kt, int stage){
        uint32_t sbase = sb + stage*STG;
        size_t ko = (size_t)kt * 64;
        #pragma unroll
        for (int t = 0; t < 2; t++)
            #pragma unroll
            for (int hh = 0; hh < 2; hh++)
                cp16(sbase + t*TILE_BYTES + soff[hh], gbase[t][hh] + ko);
        asm volatile("cp.async.commit_group;" ::: "memory");
    };

    uint32_t a_row = wm*64 + (lane & 15);
    uint32_t a_ch0 = (lane >> 4) & 1;
    uint32_t b_row = wn*32 + ((lane >> 4) & 1)*8 + (lane & 7);
    uint32_t b_ch0 = (lane >> 3) & 1;

    auto compute = [&](int kt){
        uint32_t st = sb + (kt % NST)*STG;
        #pragma unroll
        for (uint32_t j = 0; j < 2; j++){
            uint32_t ca = j*2 + a_ch0;
            uint32_t cb = j*2 + b_ch0;
            uint32_t a[4][4], b[2][4];
            #pragma unroll
            for (uint32_t q = 0; q < 2; q++)
                ldsm4(b[q], st + TILE_BYTES + swz(b_row + q*16, cb));
            #pragma unroll
            for (uint32_t i = 0; i < 4; i++)
                ldsm4(a[i], st + swz(a_row + i*16, ca));
            #pragma unroll
            for (int i = 0; i < 4; i++)
                #pragma unroll
                for (int f = 0; f < 4; f++)
                    mma_f16(acc[i][f], a[i], &b[f>>1][(f&1)*2]);
        }
    };

    issue(0, 0);
    issue(1, 1);
    issue(2, 2);
    issue(3, 3);
    for (int kt = 0; kt < KT; kt += 2){
        if (kt + 2 < KT) asm volatile("cp.async.wait_group 2;" ::: "memory");
        else             asm volatile("cp.async.wait_group 0;" ::: "memory");
        __syncthreads();
        if (kt + 4 < KT){
            issue(kt + 4, (kt + 4) % NST);
            issue(kt + 5, (kt + 5) % NST);
        }
        compute(kt);
        compute(kt + 1);
    }
}

// f32 epilogue (out): C = acc + bias
__device__ __forceinline__ void epi_f32(float acc[4][4][4], float* C, const float* bias,
                                        int m0, int n0, int wm, int wn, int lane)
{
    int mb = m0 + wm*64 + (lane >> 2);
    int nb = n0 + wn*32 + (lane & 3)*2;
    #pragma unroll
    for (int i = 0; i < 4; i++){
        #pragma unroll
        for (int f = 0; f < 4; f++){
            int row = mb + i*16;
            int col = nb + f*8;
            float v0 = acc[i][f][0], v1 = acc[i][f][1];
            float v2 = acc[i][f][2], v3 = acc[i][f][3];
            float b0 = __ldg(bias + col), b1 = __ldg(bias + col + 1);
            v0 += b0; v1 += b1; v2 += b0; v3 += b1;
            float2 o0; o0.x = v0; o0.y = v1;
            float2 o1; o1.x = v2; o1.y = v3;
            *(float2*)(C + (size_t)row * DQ + col)       = o0;
            *(float2*)(C + (size_t)(row + 8) * DQ + col) = o1;
        }
    }
}

// fp16 sigmoid epilogue (qsig)
__device__ __forceinline__ void epi_qsig(float acc[4][4][4], __half* C, const float* bias,
                                         int m0, int n0, int wm, int wn, int lane)
{
    int mb = m0 + wm*64 + (lane >> 2);
    int nb = n0 + wn*32 + (lane & 3)*2;
    #pragma unroll
    for (int i = 0; i < 4; i++){
        #pragma unroll
        for (int f = 0; f < 4; f++){
            int row = mb + i*16;
            int col = nb + f*8;
            float b0 = __ldg(bias + col), b1 = __ldg(bias + col + 1);
            float v0 = 1.f/(1.f+expf(-(acc[i][f][0] + b0)));
            float v1 = 1.f/(1.f+expf(-(acc[i][f][1] + b1)));
            float v2 = 1.f/(1.f+expf(-(acc[i][f][2] + b0)));
            float v3 = 1.f/(1.f+expf(-(acc[i][f][3] + b1)));
            __half2 o0 = __floats2half2_rn(v0, v1);
            __half2 o1 = __floats2half2_rn(v2, v3);
            *(__half2*)(C + (size_t)row * DQ + col)       = o0;
            *(__half2*)(C + (size_t)(row + 8) * DQ + col) = o1;
        }
    }
}

// ------------------------------ proj kernel ---------------------------------
__global__ void __launch_bounds__(256, 2)
proj_k(const float* __restrict__ bq, const float* __restrict__ bk,
       const float* __restrict__ bv)
{
    extern __shared__ char smem[];
    uint32_t sb = smem_u32(smem);
    int tid = threadIdx.x, wid = tid >> 5, lane = tid & 31;
    int wm = wid & 1, wn = wid >> 1;
    int m0 = blockIdx.x * 128;

    float acc[4][4][4];
    #pragma unroll
    for (int i = 0; i < 4; i++)
        #pragma unroll
        for (int f = 0; f < 4; f++)
            #pragma unroll
            for (int r = 0; r < 4; r++) acc[i][f][r] = 0.f;

    const char *B0, *B1;
    if (blockIdx.y < 8){
        size_t n0 = (size_t)blockIdx.y * 128;
        B0 = (const char*)(g_wt[0] + n0*DQ);
        B1 = B0 + (size_t)64*DQ*2;
    } else {
        size_t d0 = (size_t)(blockIdx.y - 8) * 64;
        B0 = (const char*)(g_wt[1] + d0*DQ);
        B1 = (const char*)(g_wt[2] + d0*DQ);
    }
    mma_mainloop(sb, (const char*)g_xh, B0, B1, DQ, m0, tid, wm, wn, lane, acc);

    if (blockIdx.y < 8){
        epi_qsig(acc, g_qsig, bq, m0, (int)blockIdx.y*128, wm, wn, lane);
        return;
    }

    // ---- K|V epilogue: ek = exp(K+bk), ekv = ek*(V+bv), write transposed ----
    int d0 = ((int)blockIdx.y - 8) * 64;
    float* se = (float*)smem;                 // [128][129]
    __syncthreads();
    int mbL = wm*64 + (lane >> 2);
    int nbL = wn*32 + (lane & 3)*2;
    #pragma unroll
    for (int i = 0; i < 4; i++){
        #pragma unroll
        for (int f = 0; f < 4; f++){
            int row = mbL + i*16, col = nbL + f*8;
            float v0 = acc[i][f][0], v1 = acc[i][f][1];
            float v2 = acc[i][f][2], v3 = acc[i][f][3];
            if (col < 64){
                float b0 = __ldg(bk + d0 + col), b1 = __ldg(bk + d0 + col + 1);
                v0 = expf(v0 + b0); v1 = expf(v1 + b1);
                v2 = expf(v2 + b0); v3 = expf(v3 + b1);
            } else {
                float b0 = __ldg(bv + d0 + col - 64), b1 = __ldg(bv + d0 + col - 63);
                v0 += b0; v1 += b1; v2 += b0; v3 += b1;
            }
            se[row*129 + col]     = v0; se[row*129 + col + 1]     = v1;
            se[(row+8)*129 + col] = v2; se[(row+8)*129 + col + 1] = v3;
        }
    }
    __syncthreads();

    int b  = m0 >> 11, s0 = m0 & 2047;
    int d  = tid & 63, sblk = (tid >> 6) * 32;
    __half* pk  = g_ekt  + (size_t)b*PERB + (size_t)(d0 + d)*TQ + s0 + sblk;
    __half* pkv = g_ekvt + (size_t)b*PERB + (size_t)(d0 + d)*TQ + s0 + sblk;
    float psk = 0.f, pskv = 0.f;
    #pragma unroll
    for (int gq = 0; gq < 4; gq++){
        __align__(16) __half hk[8];
        __align__(16) __half hv[8];
        #pragma unroll
        for (int s = 0; s < 8; s++){
            int sr = sblk + gq*8 + s;
            float e  = se[sr*129 + d];
            float vv = se[sr*129 + d + 64];
            __half h0 = __float2half(e);
            __half h1 = __float2half(e * vv);
            hk[s] = h0; hv[s] = h1;
            psk  += __half2float(h0);
            pskv += __half2float(h1);
        }
        *(uint4*)(pk  + gq*8) = *(const uint4*)hk;
        *(uint4*)(pkv + gq*8) = *(const uint4*)hv;
    }

    // deterministic partial colsum: 4 s-groups -> 1 per (d, CTA)
    float* pr = (float*)smem + 128*129;       // [2][4][64]
    __syncthreads();
    pr[(tid >> 6)*64 + d]       = psk;
    pr[256 + (tid >> 6)*64 + d] = pskv;
    __syncthreads();
    if (tid < 128){
        int which = tid >> 6, dl = tid & 63;
        const float* p = pr + which*256;
        float s = p[dl] + p[64 + dl] + p[128 + dl] + p[192 + dl];
        (which ? g_partkv : g_partk)[(size_t)blockIdx.x*DQ + d0 + dl] = s;
    }
}

// ---------------------- colsum reduce (16 partials) --------------------------
__global__ void k_colsum_red(){
    int i = blockIdx.x*256 + threadIdx.x;     // 0..8191
    int which = i >> 12;                      // 0: k, 1: kv
    int bd = i & 4095;
    int b = bd >> 10, dd = bd & 1023;
    const float* src = (which ? g_partkv : g_partk);
    float s = 0.f;
    #pragma unroll
    for (int j = 0; j < 16; j++)
        s += src[(size_t)(b*16 + j)*DQ + dd];
    (which ? g_sumkv : g_sumk)[bd] = s;
}

// ------------------------------- mix kernel ---------------------------------
// ONE pass: acc = (ew-1) @ [ekvt|ekt]^T ; epilogue adds colsums, op = q*num/den
__global__ void __launch_bounds__(256, 2)
mix_k()
{
    extern __shared__ char smem[];
    uint32_t sb = smem_u32(smem);
    int tid = threadIdx.x, wid = tid >> 5, lane = tid & 31;
    int wm = wid & 1, wn = wid >> 1;
    int t0 = blockIdx.x * 128;
    int d0 = blockIdx.y * 64;
    int b  = blockIdx.z;

    float acc[4][4][4];
    #pragma unroll
    for (int i = 0; i < 4; i++)
        #pragma unroll
        for (int f = 0; f < 4; f++)
            #pragma unroll
            for (int r = 0; r < 4; r++) acc[i][f][r] = 0.f;

    const char* B0 = (const char*)(g_ekvt + (size_t)b*PERB + (size_t)d0*TQ);
    const char* B1 = (const char*)(g_ekt  + (size_t)b*PERB + (size_t)d0*TQ);
    mma_mainloop(sb, (const char*)g_ewc, B0, B1, TQ, t0, tid, wm, wn, lane, acc);

    float* se = (float*)smem;                 // [128][129]
    __syncthreads();
    int mbL = wm*64 + (lane >> 2);
    int nbL = wn*32 + (lane & 3)*2;
    #pragma unroll
    for (int i = 0; i < 4; i++){
        #pragma unroll
        for (int f = 0; f < 4; f++){
            int row = mbL + i*16, col = nbL + f*8;
            se[row*129 + col]     = acc[i][f][0]; se[row*129 + col + 1]     = acc[i][f][1];
            se[(row+8)*129 + col] = acc[i][f][2]; se[(row+8)*129 + col + 1] = acc[i][f][3];
        }
    }
    __syncthreads();

    int t = tid >> 1, dq = (tid & 1) * 32;
    size_t obase = (size_t)b*PERB + (size_t)(t0 + t)*DQ + d0 + dq;
    const __half* qp = g_qsig + obase;
    const float* skv = g_sumkv + b*DQ + d0 + dq;
    const float* sk  = g_sumk  + b*DQ + d0 + dq;
    __half* ph = g_oph + obase;
    #pragma unroll
    for (int gq = 0; gq < 4; gq++){
        __align__(16) __half hh[8];
        uint4 qu = *(const uint4*)(qp + gq*8);
        const __half2* qh2 = (const __half2*)&qu;
        #pragma unroll
        for (int s = 0; s < 8; s++){
            int c = dq + gq*8 + s;
            float num = se[t*129 + c]      + __ldg(skv + gq*8 + s);
            float den = se[t*129 + 64 + c] + __ldg(sk  + gq*8 + s);
            float q   = ((s & 1) ? __high2float(qh2[s >> 1]) : __low2float(qh2[s >> 1]));
            hh[s] = __float2half(q * num / den);
        }
        *(uint4*)(ph + gq*8) = *(const uint4*)hh;
    }
}

// ------------------------------- out kernel ---------------------------------
__global__ void __launch_bounds__(256, 2)
out_k(float* __restrict__ out, const float* __restrict__ bo)
{
    extern __shared__ char smem[];
    uint32_t sb = smem_u32(smem);
    int tid = threadIdx.x, wid = tid >> 5, lane = tid & 31;
    int wm = wid & 1, wn = wid >> 1;
    int m0 = blockIdx.x * 128, n0 = blockIdx.y * 128;

    float acc[4][4][4];
    #pragma unroll
    for (int i = 0; i < 4; i++)
        #pragma unroll
        for (int f = 0; f < 4; f++)
            #pragma unroll
            for (int r = 0; r < 4; r++) acc[i][f][r] = 0.f;

    const char* B0 = (const char*)(g_wt[3] + (size_t)n0*DQ);
    const char* B1 = B0 + (size_t)64*DQ*2;
    mma_mainloop(sb, (const char*)g_oph, B0, B1, DQ, m0, tid, wm, wn, lane, acc);
    epi_f32(acc, out, bo, m0, n0, wm, wn, lane);
}

// --------------------------- fused input prep --------------------------------
// blocks 0..4095    : transpose W_z 32x32 tiles -> g_wt[z] (fp16)
// blocks 4096..12287: x -> g_xh (fp16)
// blocks 12288..16383: wbias -> g_ewc = fp16(expm1(wbias))
__global__ void k_prep_all(const float* __restrict__ W0, const float* __restrict__ W1,
                           const float* __restrict__ W2, const float* __restrict__ W3,
                           const float* __restrict__ x,  const float* __restrict__ wb){
    __shared__ float t[32][33];
    uint32_t blk = blockIdx.x;
    int tid = threadIdx.x;
    if (blk < 4096){
        int z  = blk >> 10;
        int r  = blk & 1023;
        int bx = r & 31, by = r >> 5;
        const float* W = (z == 0) ? W0 : (z == 1) ? W1 : (z == 2) ? W2 : W3;
        __half* tw = g_wt[z];
        int tx = tid & 31, ty = tid >> 5;
        int xc = bx*32 + tx;
        int y0 = by*32;
        for (int j = ty; j < 32; j += 8)
            t[j][tx] = W[(size_t)(y0 + j)*DQ + xc];
        __syncthreads();
        int x2  = y0 + tx;
        int y20 = bx*32;
        for (int j = ty; j < 32; j += 8)
            tw[(size_t)(y20 + j)*DQ + x2] = __float2half(t[tx][j]);
    } else if (blk < 12288){
        size_t i = (size_t)(blk - 4096) * 256 + tid;
        float4 v = ((const float4*)x)[i];
        ((uint2*)g_xh)[i] = make_uint2(pk2h(__float2half(v.x), __float2half(v.y)),
                                       pk2h(__float2half(v.z), __float2half(v.w)));
    } else {
        size_t i = (size_t)(blk - 12288) * 256 + tid;
        float4 v = ((const float4*)wb)[i];
        ((uint2*)g_ewc)[i] = make_uint2(
            pk2h(__float2half(expm1f(v.x)), __float2half(expm1f(v.y))),
            pk2h(__float2half(expm1f(v.z)), __float2half(expm1f(v.w))));
    }
}

// --------------------------------- host -------------------------------------
extern "C" void kernel_launch(void* const* d_in, const int* in_sizes, int n_in,
                              void* d_out, int out_size){
    (void)in_sizes; (void)n_in; (void)out_size;
    const float* x  = (const float*)d_in[0];
    const float* Wq = (const float*)d_in[1];
    const float* bq = (const float*)d_in[2];
    const float* Wk = (const float*)d_in[3];
    const float* bk = (const float*)d_in[4];
    const float* Wv = (const float*)d_in[5];
    const float* bv = (const float*)d_in[6];
    const float* Wo = (const float*)d_in[7];
    const float* bo = (const float*)d_in[8];
    const float* wb = (const float*)d_in[9];
    float* out = (float*)d_out;

    cudaFuncSetAttribute(proj_k, cudaFuncAttributeMaxDynamicSharedMemorySize, GEMM_SMEM);
    cudaFuncSetAttribute(mix_k,  cudaFuncAttributeMaxDynamicSharedMemorySize, GEMM_SMEM);
    cudaFuncSetAttribute(out_k,  cudaFuncAttributeMaxDynamicSharedMemorySize, GEMM_SMEM);

    // fused prep: weight transposes + x/wbias fp16 conversion (one launch)
    k_prep_all<<<16384, 256>>>(Wq, Wk, Wv, Wo, x, wb);

    // proj: y<8 qsig (fp16), y>=8 fused K|V -> ekt/ekvt + partial colsums
    proj_k<<<dim3(64, 24), 256, GEMM_SMEM>>>(bq, bk, bv);

    // reduce 16 partials -> colsums
    k_colsum_red<<<32, 256>>>();

    // mix: single-pass centered GEMM + colsum correction + op epilogue
    mix_k<<<dim3(16, 16, 4), 256, GEMM_SMEM>>>();

    // out = OP @ Wo + bo (single-pass fp16)
    out_k<<<dim3(64, 8), 256, GEMM_SMEM>>>(out, bo);
}